// round 6
// baseline (speedup 1.0000x reference)
#include <cuda_runtime.h>

#define Wd 192
#define Hd 192
#define HW (Wd * Hd)
#define Hm 190
#define Wm 190
#define Lm (Hm * Wm)
#define NBG 32   // B*G = 2*16

// Scratch (device globals; no runtime allocation)
__device__ double g_gram[NBG * 9 * 64];  // full 8x8 gram per (bg, j)
__device__ int    g_nnA[NBG * 9];        // neighbor channel-in-group
__device__ int    g_nnK[NBG * 9];        // neighbor 3x3 offset index
__device__ float  g_cnt[NBG * 9];        // count (as float)

// ---------------------------------------------------------------------------
// Kernel A: per (bg, j) compute the 8x8 gram of motif rows over L=190*190.
// Motif row c -> flat F=8j+c -> (a=F/9, k=F%9); value = feat[a, k/3+y, k%3+x].
// ---------------------------------------------------------------------------
__global__ __launch_bounds__(256) void motif_gram_kernel(const float* __restrict__ f) {
    const int blk = blockIdx.x;       // 0..287
    const int bg  = blk / 9;
    const int j   = blk % 9;
    const int b   = bg / 16, g = bg % 16;
    const float* fb = f + ((size_t)b * 128 + (size_t)g * 8) * HW;

    int off[8];
#pragma unroll
    for (int c = 0; c < 8; c++) {
        int F = 8 * j + c;
        int a = F / 9, k = F % 9;
        off[c] = a * HW + (k / 3) * Wd + (k % 3);
    }

    float acc[36];
#pragma unroll
    for (int t = 0; t < 36; t++) acc[t] = 0.f;

    for (int l = threadIdx.x; l < Lm; l += 256) {
        const int pos = l + 2 * (l / Wm);   // y*192 + x  where y=l/190, x=l%190
        float m[8];
#pragma unroll
        for (int c = 0; c < 8; c++) m[c] = fb[off[c] + pos];
        int t = 0;
#pragma unroll
        for (int c = 0; c < 8; c++)
#pragma unroll
            for (int d = c; d < 8; d++) {
                acc[t] += m[c] * m[d];
                t++;
            }
    }

    // warp reduce (f32), then cross-warp in double
    const int lane = threadIdx.x & 31, wid = threadIdx.x >> 5;
#pragma unroll
    for (int t = 0; t < 36; t++) {
#pragma unroll
        for (int s = 16; s > 0; s >>= 1)
            acc[t] += __shfl_down_sync(0xffffffffu, acc[t], s);
    }

    __shared__ float part[8][36];
    if (lane == 0) {
#pragma unroll
        for (int t = 0; t < 36; t++) part[wid][t] = acc[t];
    }
    __syncthreads();

    if (threadIdx.x < 36) {
        double s = 0.0;
        for (int w8 = 0; w8 < 8; w8++) s += (double)part[w8][threadIdx.x];
        // unpack triangular index -> (c, d)
        int rem = threadIdx.x, c = 0;
        while (rem >= 8 - c) { rem -= (8 - c); c++; }
        int d = c + rem;
        double* gb = g_gram + (size_t)blk * 64;
        gb[c * 8 + d] = s;
        gb[d * 8 + c] = s;
    }
}

// ---------------------------------------------------------------------------
// Kernel B: per bg, per (j,c): argmin_d d2 (diag=inf, first-min tie-break);
// per j: u = max_c nn, cnt = #{nn==u}; store neighbor (a, k) and cnt.
// ---------------------------------------------------------------------------
__global__ __launch_bounds__(128) void motif_argmin_kernel() {
    const int bg = blockIdx.x;
    __shared__ int nn[72];
    const int t = threadIdx.x;

    if (t < 72) {
        const int j = t / 8, c = t % 8;
        const double* gj = g_gram + (size_t)(bg * 9 + j) * 64;
        const double scc = gj[c * 8 + c];
        double best = 1e300;
        int bi = 0;
        for (int d = 0; d < 8; d++) {
            if (d == c) continue;
            double d2 = scc + gj[d * 8 + d] - 2.0 * gj[c * 8 + d];
            if (d2 < best) { best = d2; bi = d; }
        }
        nn[t] = bi;
    }
    __syncthreads();

    if (t < 9) {
        int u = 0, cnt = 0;
        for (int c = 0; c < 8; c++) u = max(u, nn[t * 8 + c]);
        for (int c = 0; c < 8; c++) cnt += (nn[t * 8 + c] == u) ? 1 : 0;
        const int fn = 8 * t + u;
        g_nnA[bg * 9 + t] = fn / 9;
        g_nnK[bg * 9 + t] = fn % 9;
        g_cnt[bg * 9 + t] = (float)cnt;
    }
}

// ---------------------------------------------------------------------------
// Kernel C: gather form of the fold. One block per (b, global channel).
// out[h,w] = mask*nvalid*self + sum over valid knew of
//            floor(((self * nb[knew]) * cnt_j) * 0.125f)
// nb address = self + precomputed constant offset (always in-bounds).
// ---------------------------------------------------------------------------
__global__ __launch_bounds__(256) void motif_out_kernel(const float* __restrict__ f,
                                                        float* __restrict__ out) {
    const int bc = blockIdx.x;        // 0..255 = b*128 + cglob
    const int b = bc >> 7, cglob = bc & 127;
    const int g = cglob >> 3, cnew = cglob & 7;
    const int bg = b * 16 + g;

    __shared__ int   off9[9];
    __shared__ float cnt9[9];
    if (threadIdx.x < 9) {
        const int knew = threadIdx.x;
        const int j = (cnew * 9 + knew) >> 3;
        const int an = g_nnA[bg * 9 + j];
        const int kn = g_nnK[bg * 9 + j];
        cnt9[knew] = g_cnt[bg * 9 + j];
        const int dh = kn / 3 - knew / 3;
        const int dw = kn % 3 - knew % 3;
        off9[knew] = (an - cnew) * HW + dh * Wd + dw;
    }
    __syncthreads();

    const float* fc = f + (size_t)bc * HW;
    float* oc = out + (size_t)bc * HW;
    const float mask = (b != 0) ? 1.0f : 0.0f;

    for (int idx = threadIdx.x; idx < HW; idx += 256) {
        const int h = idx / Wd;
        const int w = idx - h * Wd;
        const float self = fc[idx];
        float acc = 0.f;
        int nvalid;

        if (h >= 2 && h <= Hd - 3 && w >= 2 && w <= Wd - 3) {
            nvalid = 9;
#pragma unroll
            for (int k = 0; k < 9; k++) {
                const float nb = fc[idx + off9[k]];
                float tv = self * nb;     // exact op order matches reference
                tv = tv * cnt9[k];
                tv = tv * 0.125f;         // /8 is exact
                acc += floorf(tv);
            }
        } else {
            const int kiLo = max(0, h - (Hm - 1)), kiHi = min(2, h);
            const int kjLo = max(0, w - (Wm - 1)), kjHi = min(2, w);
            nvalid = (kiHi - kiLo + 1) * (kjHi - kjLo + 1);
            for (int ki = kiLo; ki <= kiHi; ki++)
                for (int kj = kjLo; kj <= kjHi; kj++) {
                    const int k = ki * 3 + kj;
                    const float nb = fc[idx + off9[k]];
                    float tv = self * nb;
                    tv = tv * cnt9[k];
                    tv = tv * 0.125f;
                    acc += floorf(tv);
                }
        }
        oc[idx] = acc + mask * (float)nvalid * self;
    }
}

extern "C" void kernel_launch(void* const* d_in, const int* in_sizes, int n_in,
                              void* d_out, int out_size) {
    const float* f = (const float*)d_in[0];
    float* out = (float*)d_out;
    (void)in_sizes; (void)n_in; (void)out_size;

    motif_gram_kernel<<<288, 256>>>(f);
    motif_argmin_kernel<<<32, 128>>>();
    motif_out_kernel<<<256, 256>>>(f, out);
}

// round 7
// speedup vs baseline: 1.2150x; 1.2150x over previous
#include <cuda_runtime.h>

#define Wd 192
#define Hd 192
#define HW (Wd * Hd)
#define Hm 190
#define Wm 190
#define NBG 32     // B*G = 2*16
#define SPLIT 5
#define RS 38      // rows per slice (190/5)

// Scratch (device globals; no runtime allocation)
__device__ double g_part[288 * SPLIT * 36];  // partial triangular grams
__device__ int    g_nnA[NBG * 9];
__device__ int    g_nnK[NBG * 9];
__device__ float  g_cnt[NBG * 9];

typedef unsigned long long ull;

__device__ __forceinline__ ull pack2(float lo, float hi) {
    ull r;
    asm("mov.b64 %0, {%1, %2};" : "=l"(r) : "f"(lo), "f"(hi));
    return r;
}
__device__ __forceinline__ void unpack2(ull v, float& lo, float& hi) {
    asm("mov.b64 {%0, %1}, %2;" : "=f"(lo), "=f"(hi) : "l"(v));
}
__device__ __forceinline__ void fma2(ull& d, ull a, ull b) {
    asm("fma.rn.f32x2 %0, %1, %2, %0;" : "+l"(d) : "l"(a), "l"(b));
}

// ---------------------------------------------------------------------------
// Kernel A: per (bg, j, row-slice) partial 8x8 gram of motif rows.
// Motif row c -> flat F=8j+c -> (a=F/9, k=F%9); value = feat[a, k/3+y, k%3+x].
// Thread = column x (0..189); packed f32x2 FMA over row pairs.
// ---------------------------------------------------------------------------
__global__ __launch_bounds__(192) void motif_gram_kernel(const float* __restrict__ f) {
    const int blk = blockIdx.x;       // 0..287 = bg*9 + j
    const int sl  = blockIdx.y;       // 0..4
    const int bg  = blk / 9;
    const int j   = blk % 9;
    const float* fb = f + (size_t)bg * 8 * HW;   // b*128 + g*8 == bg*8

    int off[8];
#pragma unroll
    for (int c = 0; c < 8; c++) {
        const int F = 8 * j + c;
        const int a = F / 9, k = F % 9;
        off[c] = a * HW + (k / 3) * Wd + (k % 3);
    }

    ull acc[36];
#pragma unroll
    for (int t = 0; t < 36; t++) acc[t] = 0ull;

    const int w = threadIdx.x;
    if (w < Wm) {
        const int y0 = sl * RS;
#pragma unroll 1
        for (int yy = 0; yy < RS; yy += 2) {
            const int base0 = (y0 + yy) * Wd + w;
            const int base1 = base0 + Wd;
            ull m[8];
#pragma unroll
            for (int c = 0; c < 8; c++) {
                const float a0 = fb[off[c] + base0];
                const float a1 = fb[off[c] + base1];
                m[c] = pack2(a0, a1);
            }
            int t = 0;
#pragma unroll
            for (int c = 0; c < 8; c++)
#pragma unroll
                for (int d = c; d < 8; d++) {
                    fma2(acc[t], m[c], m[d]);
                    t++;
                }
        }
    }

    // per-thread combine + warp shuffle reduce (6 full warps)
    float s[36];
#pragma unroll
    for (int t = 0; t < 36; t++) {
        float lo, hi;
        unpack2(acc[t], lo, hi);
        s[t] = lo + hi;
    }
    const int lane = threadIdx.x & 31, wid = threadIdx.x >> 5;
#pragma unroll
    for (int t = 0; t < 36; t++) {
#pragma unroll
        for (int sh = 16; sh > 0; sh >>= 1)
            s[t] += __shfl_down_sync(0xffffffffu, s[t], sh);
    }

    __shared__ float part[6][36];
    if (lane == 0) {
#pragma unroll
        for (int t = 0; t < 36; t++) part[wid][t] = s[t];
    }
    __syncthreads();

    if (threadIdx.x < 36) {
        double acc_d = 0.0;
#pragma unroll
        for (int w6 = 0; w6 < 6; w6++) acc_d += (double)part[w6][threadIdx.x];
        g_part[((size_t)blk * SPLIT + sl) * 36 + threadIdx.x] = acc_d;
    }
}

// ---------------------------------------------------------------------------
// Kernel B: reduce slice partials -> full grams; argmin (diag excluded,
// first-min tie-break); per j: u = max nn, cnt = #{nn==u}.
// ---------------------------------------------------------------------------
__global__ __launch_bounds__(128) void motif_argmin_kernel() {
    const int bg = blockIdx.x;
    const int t  = threadIdx.x;
    __shared__ double G[9 * 64];
    __shared__ int nn[72];

    for (int e = t; e < 9 * 36; e += 128) {
        const int j = e / 36;
        int rem = e % 36, c = 0;
        while (rem >= 8 - c) { rem -= (8 - c); c++; }
        const int d = c + rem;
        double sum = 0.0;
#pragma unroll
        for (int sl = 0; sl < SPLIT; sl++)
            sum += g_part[((size_t)(bg * 9 + j) * SPLIT + sl) * 36 + (e % 36)];
        G[j * 64 + c * 8 + d] = sum;
        G[j * 64 + d * 8 + c] = sum;
    }
    __syncthreads();

    if (t < 72) {
        const int j = t / 8, c = t % 8;
        const double* gj = G + j * 64;
        const double scc = gj[c * 8 + c];
        double best = 1e300;
        int bi = 0;
        for (int d = 0; d < 8; d++) {
            if (d == c) continue;
            const double d2 = scc + gj[d * 8 + d] - 2.0 * gj[c * 8 + d];
            if (d2 < best) { best = d2; bi = d; }
        }
        nn[t] = bi;
    }
    __syncthreads();

    if (t < 9) {
        int u = 0, cnt = 0;
        for (int c = 0; c < 8; c++) u = max(u, nn[t * 8 + c]);
        for (int c = 0; c < 8; c++) cnt += (nn[t * 8 + c] == u) ? 1 : 0;
        const int fn = 8 * t + u;
        g_nnA[bg * 9 + t] = fn / 9;
        g_nnK[bg * 9 + t] = fn % 9;
        g_cnt[bg * 9 + t] = (float)cnt;
    }
}

// ---------------------------------------------------------------------------
// Kernel C: gather form of the fold. Grid (256 planes, 4 row-slices).
// out[h,w] = mask*nvalid*self + sum over valid knew of
//            floor(((self * nb) * cnt_j) * 0.125f)
// ---------------------------------------------------------------------------
__global__ __launch_bounds__(256) void motif_out_kernel(const float* __restrict__ f,
                                                        float* __restrict__ out) {
    const int bc = blockIdx.x;        // b*128 + cglob
    const int b = bc >> 7, cglob = bc & 127;
    const int g = cglob >> 3, cnew = cglob & 7;
    const int bg = b * 16 + g;

    __shared__ int   off9[9];
    __shared__ float cnt9[9];
    if (threadIdx.x < 9) {
        const int knew = threadIdx.x;
        const int j = (cnew * 9 + knew) >> 3;
        const int an = g_nnA[bg * 9 + j];
        const int kn = g_nnK[bg * 9 + j];
        cnt9[knew] = g_cnt[bg * 9 + j];
        const int dh = kn / 3 - knew / 3;
        const int dw = kn % 3 - knew % 3;
        off9[knew] = (an - cnew) * HW + dh * Wd + dw;
    }
    __syncthreads();

    const float* fc = f + (size_t)bc * HW;
    float* oc = out + (size_t)bc * HW;
    const float mask = (b != 0) ? 1.0f : 0.0f;

    const int start = blockIdx.y * (HW / 4);
    const int end   = start + (HW / 4);

    for (int idx = start + threadIdx.x; idx < end; idx += 256) {
        const int h = idx / Wd;
        const int w = idx - h * Wd;
        const float self = fc[idx];
        float acc = 0.f;
        int nvalid;

        if (h >= 2 && h <= Hd - 3 && w >= 2 && w <= Wd - 3) {
            nvalid = 9;
#pragma unroll
            for (int k = 0; k < 9; k++) {
                const float nb = fc[idx + off9[k]];
                float tv = self * nb;     // exact op order matches reference
                tv = tv * cnt9[k];
                tv = tv * 0.125f;         // /8 exact
                acc += floorf(tv);
            }
        } else {
            const int kiLo = max(0, h - (Hm - 1)), kiHi = min(2, h);
            const int kjLo = max(0, w - (Wm - 1)), kjHi = min(2, w);
            nvalid = (kiHi - kiLo + 1) * (kjHi - kjLo + 1);
            for (int ki = kiLo; ki <= kiHi; ki++)
                for (int kj = kjLo; kj <= kjHi; kj++) {
                    const int k = ki * 3 + kj;
                    const float nb = fc[idx + off9[k]];
                    float tv = self * nb;
                    tv = tv * cnt9[k];
                    tv = tv * 0.125f;
                    acc += floorf(tv);
                }
        }
        oc[idx] = acc + mask * (float)nvalid * self;
    }
}

extern "C" void kernel_launch(void* const* d_in, const int* in_sizes, int n_in,
                              void* d_out, int out_size) {
    const float* f = (const float*)d_in[0];
    float* out = (float*)d_out;
    (void)in_sizes; (void)n_in; (void)out_size;

    motif_gram_kernel<<<dim3(288, SPLIT), 192>>>(f);
    motif_argmin_kernel<<<32, 128>>>();
    motif_out_kernel<<<dim3(256, 4), 256>>>(f, out);
}